// round 3
// baseline (speedup 1.0000x reference)
#include <cuda_runtime.h>

// ---------------------------------------------------------------------------
// WindowedCrossAttention (Swin-style window cross attention)
//   B=4096 windows, N=64 tokens, C=256, H=8 heads, d=32
// Decomposition:
//   1) bias precompute:   g_bias[h][n][m] = bias_table[relidx(n,m)][h]
//   2) GEMM:  Q  = (Xq @ Wq + bq) * d^-0.5          [M=B*64, 256]
//   3) GEMM:  KV =  Xs @ Wkv + bkv                  [M, 512] (K cols 0..255, V 256..511)
//   4) attention per (window, head): softmax(QK^T + bias) @ V -> g_O
//   5) GEMM:  out = g_O @ Wp + bp                   [M, 256]
// All fp32 math; GEMM inner loop uses packed fma.rn.f32x2 (2x FFMA rate).
// R2 fix: bias_kernel grid was 32 blocks (8192 threads) for 32768 elements;
//         3/4 of g_bias stayed zero -> rel_err 1.7e-2. Now 128 blocks.
// ---------------------------------------------------------------------------

// Device-global scratch (static allocations are module-load time; allowed).
__device__ float g_Q [4096ull * 64ull * 256ull];   // 268 MB
__device__ float g_KV[4096ull * 64ull * 512ull];   // 537 MB
__device__ float g_O [4096ull * 64ull * 256ull];   // 268 MB
__device__ float g_bias[8 * 64 * 64];              // 128 KB

// ---- packed f32x2 helpers --------------------------------------------------
__device__ __forceinline__ unsigned long long pk2(float x) {
    unsigned long long r;
    asm("mov.b64 %0, {%1, %1};" : "=l"(r) : "r"(__float_as_uint(x)));
    return r;
}
__device__ __forceinline__ void fma2(unsigned long long& d, unsigned long long a,
                                     unsigned long long b) {
    asm("fma.rn.f32x2 %0, %1, %2, %0;" : "+l"(d) : "l"(a), "l"(b));
}
__device__ __forceinline__ void unpk(unsigned long long v, float& lo, float& hi) {
    unsigned int l, h;
    asm("mov.b64 {%0, %1}, %2;" : "=r"(l), "=r"(h) : "l"(v));
    lo = __uint_as_float(l);
    hi = __uint_as_float(h);
}

// ---- relative-position bias precompute --------------------------------------
__global__ void bias_kernel(const float* __restrict__ bt) {
    int idx = blockIdx.x * 256 + threadIdx.x;          // 0 .. 32767
    if (idx >= 8 * 64 * 64) return;
    int h  = idx >> 12;
    int nm = idx & 4095;
    int n = nm >> 6, m = nm & 63;
    int dy = (n >> 3) - (m >> 3);
    int dx = (n & 7) - (m & 7);
    int r  = (dy + 7) * 15 + (dx + 7);
    g_bias[idx] = bt[r * 8 + h];
}

// ---- tiled fp32 GEMM: C[M,N] = scale * (A[M,256] @ W[256,N] + bias) ---------
// BM=128, BN=128, BK=16, 256 threads, 8x8 per-thread tile, f32x2 accumulators.
// SRCSEL: 0 -> A param, 1 -> g_O.   DSTSEL: 0 -> g_Q, 1 -> g_KV, 2 -> C param.
template <int N, int DSTSEL, int SRCSEL>
__global__ __launch_bounds__(256, 2)
void gemm_kernel(const float* __restrict__ Ap, const float* __restrict__ W,
                 const float* __restrict__ bias, float* __restrict__ Cp,
                 float scale) {
    const float* A = (SRCSEL == 0) ? Ap : g_O;
    float* C = (DSTSEL == 0) ? g_Q : ((DSTSEL == 1) ? g_KV : Cp);

    __shared__ float sA[16][128];   // [k][m]
    __shared__ float sB[16][128];   // [k][n]

    const int tid = threadIdx.x;
    const int tx = tid & 15, ty = tid >> 4;
    const int m_sub = ty * 8, n_sub = tx * 8;
    const long long m0 = (long long)blockIdx.x * 128;
    const int n0 = blockIdx.y * 128;

    unsigned long long acc[32];     // 8 m  x  4 n-pairs
#pragma unroll
    for (int i = 0; i < 32; ++i) acc[i] = 0ull;

    const int arow0 = tid >> 2;            // 0..63 (+64)
    const int akq   = (tid & 3) << 2;      // 0,4,8,12
    const int brow0 = tid >> 5;            // 0..7 (+8)
    const int bnq   = (tid & 31) << 2;     // 0..124

    for (int kt = 0; kt < 16; ++kt) {
        const int k0 = kt * 16;
        __syncthreads();
#pragma unroll
        for (int r = 0; r < 2; ++r) {
            const int row = arow0 + r * 64;
            float4 av = *reinterpret_cast<const float4*>(
                A + (m0 + row) * 256 + k0 + akq);
            sA[akq + 0][row] = av.x;
            sA[akq + 1][row] = av.y;
            sA[akq + 2][row] = av.z;
            sA[akq + 3][row] = av.w;
        }
#pragma unroll
        for (int r = 0; r < 2; ++r) {
            const int row = brow0 + r * 8;
            *reinterpret_cast<float4*>(&sB[row][bnq]) =
                *reinterpret_cast<const float4*>(
                    W + (long long)(k0 + row) * N + n0 + bnq);
        }
        __syncthreads();
#pragma unroll
        for (int kk = 0; kk < 16; ++kk) {
            float4 a0 = *reinterpret_cast<const float4*>(&sA[kk][m_sub]);
            float4 a1 = *reinterpret_cast<const float4*>(&sA[kk][m_sub + 4]);
            ulonglong2 b0 = *reinterpret_cast<const ulonglong2*>(&sB[kk][n_sub]);
            ulonglong2 b1 = *reinterpret_cast<const ulonglong2*>(&sB[kk][n_sub + 4]);
            unsigned long long bpair[4] = {b0.x, b0.y, b1.x, b1.y};
            float am[8] = {a0.x, a0.y, a0.z, a0.w, a1.x, a1.y, a1.z, a1.w};
#pragma unroll
            for (int i = 0; i < 8; ++i) {
                unsigned long long ap = pk2(am[i]);
#pragma unroll
                for (int jp = 0; jp < 4; ++jp) fma2(acc[i * 4 + jp], ap, bpair[jp]);
            }
        }
    }

    // epilogue: out = scale * (acc + bias)
#pragma unroll
    for (int i = 0; i < 8; ++i) {
        float outv[8];
#pragma unroll
        for (int jp = 0; jp < 4; ++jp) {
            float lo, hi;
            unpk(acc[i * 4 + jp], lo, hi);
            outv[jp * 2 + 0] = scale * (lo + bias[n0 + n_sub + jp * 2 + 0]);
            outv[jp * 2 + 1] = scale * (hi + bias[n0 + n_sub + jp * 2 + 1]);
        }
        float* cp = C + (m0 + m_sub + i) * N + n0 + n_sub;
        *reinterpret_cast<float4*>(cp)     = make_float4(outv[0], outv[1], outv[2], outv[3]);
        *reinterpret_cast<float4*>(cp + 4) = make_float4(outv[4], outv[5], outv[6], outv[7]);
    }
}

// ---- fused attention per (window, head) -------------------------------------
// 64 threads; thread n owns query row n. K/V/Q/bias staged in smem.
__global__ __launch_bounds__(64)
void attn_kernel() {
    __shared__ float sQ[64][33];     // padded: per-thread row reads conflict-free
    __shared__ float sK[64][32];     // broadcast reads, no pad needed
    __shared__ float sV[64][32];
    __shared__ float sBias[64][65];  // padded: [n][m] reads conflict-free

    const int w = blockIdx.x;
    const int h = blockIdx.y;
    const int tid = threadIdx.x;

    const float* qb = g_Q  + (long long)w * (64 * 256) + h * 32;
    const float* kb = g_KV + (long long)w * (64 * 512) + h * 32;
    const float* vb = kb + 256;

#pragma unroll
    for (int it = 0; it < 8; ++it) {
        int idx = tid + it * 64;        // 0..511 -> 64 rows x 8 float4
        int row = idx >> 3;
        int cq  = (idx & 7) << 2;
        float4 qv = *reinterpret_cast<const float4*>(qb + row * 256 + cq);
        sQ[row][cq + 0] = qv.x; sQ[row][cq + 1] = qv.y;
        sQ[row][cq + 2] = qv.z; sQ[row][cq + 3] = qv.w;
        *reinterpret_cast<float4*>(&sK[row][cq]) =
            *reinterpret_cast<const float4*>(kb + row * 512 + cq);
        *reinterpret_cast<float4*>(&sV[row][cq]) =
            *reinterpret_cast<const float4*>(vb + row * 512 + cq);
    }
    const float* bb = g_bias + h * 4096;
#pragma unroll
    for (int it = 0; it < 16; ++it) {
        int idx = tid + it * 64;        // 0..1023 -> 64 rows x 16 float4
        int row = idx >> 4;
        int mq  = (idx & 15) << 2;
        float4 b4 = *reinterpret_cast<const float4*>(bb + row * 64 + mq);
        sBias[row][mq + 0] = b4.x; sBias[row][mq + 1] = b4.y;
        sBias[row][mq + 2] = b4.z; sBias[row][mq + 3] = b4.w;
    }
    __syncthreads();

    const int n = tid;
    float q[32];
#pragma unroll
    for (int j = 0; j < 32; ++j) q[j] = sQ[n][j];

    float s[64];
#pragma unroll
    for (int m = 0; m < 64; ++m) {
        float acc = 0.f;
#pragma unroll
        for (int j = 0; j < 32; ++j) acc += q[j] * sK[m][j];
        s[m] = acc + sBias[n][m];
    }

    float mx = s[0];
#pragma unroll
    for (int m = 1; m < 64; ++m) mx = fmaxf(mx, s[m]);
    float sum = 0.f;
#pragma unroll
    for (int m = 0; m < 64; ++m) {
        s[m] = expf(s[m] - mx);
        sum += s[m];
    }
    const float inv = 1.f / sum;

    float o[32];
#pragma unroll
    for (int j = 0; j < 32; ++j) o[j] = 0.f;
#pragma unroll
    for (int m = 0; m < 64; ++m) {
        const float p = s[m];
#pragma unroll
        for (int j = 0; j < 32; ++j) o[j] += p * sV[m][j];
    }

    float* ob = g_O + (long long)w * (64 * 256) + n * 256 + h * 32;
#pragma unroll
    for (int jq = 0; jq < 8; ++jq) {
        *reinterpret_cast<float4*>(ob + jq * 4) =
            make_float4(o[jq * 4 + 0] * inv, o[jq * 4 + 1] * inv,
                        o[jq * 4 + 2] * inv, o[jq * 4 + 3] * inv);
    }
}

// ---------------------------------------------------------------------------
extern "C" void kernel_launch(void* const* d_in, const int* in_sizes, int n_in,
                              void* d_out, int out_size) {
    const float* xq  = (const float*)d_in[0];   // query_tokens [B,64,256]
    const float* xs  = (const float*)d_in[1];   // source_tokens [B,64,256]
    const float* Wq  = (const float*)d_in[2];   // [256,256]
    const float* bq  = (const float*)d_in[3];   // [256]
    const float* Wkv = (const float*)d_in[4];   // [256,512]
    const float* bkv = (const float*)d_in[5];   // [512]
    const float* bt  = (const float*)d_in[6];   // [(2*8-1)^2=225, 8]
    const float* Wp  = (const float*)d_in[7];   // [256,256]
    const float* bp  = (const float*)d_in[8];   // [256]
    float* out = (float*)d_out;                 // [B,64,256] f32

    const int M = in_sizes[0] / 256;            // B*64 = 262144
    const int B = M / 64;                       // 4096
    const float scale = 0.17677669529663687f;   // 32^-0.5

    bias_kernel<<<128, 256>>>(bt);              // 32768 elements (R2 fix)
    gemm_kernel<256, 0, 0><<<dim3(M / 128, 2), 256>>>(xq, Wq, bq, nullptr, scale);
    gemm_kernel<512, 1, 0><<<dim3(M / 128, 4), 256>>>(xs, Wkv, bkv, nullptr, 1.f);
    attn_kernel<<<dim3(B, 8), 64>>>();
    gemm_kernel<256, 2, 1><<<dim3(M / 128, 2), 256>>>(nullptr, Wp, bp, out, 1.f);
}

// round 5
// speedup vs baseline: 1.8936x; 1.8936x over previous
#include <cuda_runtime.h>
#include <cuda_bf16.h>
#include <cstdint>

// ---------------------------------------------------------------------------
// WindowedCrossAttention — R5: mma.sync (HMMA) bf16 hi/lo-split GEMMs
//   (tcgen05 rejected: harness emits compute_103 PTX, no 'a' target)
//   B=4096 windows, N=64 tokens, C=256, H=8 heads, d=32
//   1) bias precompute (transposed [h][m][n])
//   2) convW: W -> Wt_hi/Wt_lo (bf16, [n][k])
//   3..5) GEMMs via mma.sync.m16n8k16.bf16: C = Ah*Bh + Ah*Bl + Al*Bh
//   attention: fp32, f32x2, __expf
// ---------------------------------------------------------------------------

__device__ float g_Q [4096ull * 64ull * 256ull];
__device__ float g_KV[4096ull * 64ull * 512ull];
__device__ float g_O [4096ull * 64ull * 256ull];
__device__ float g_bias[8 * 64 * 64];                 // [h][m][n]
__device__ __nv_bfloat16 g_Wthi[512 * 256];           // [n][k]
__device__ __nv_bfloat16 g_Wtlo[512 * 256];

// ---- helpers ----------------------------------------------------------------
__device__ __forceinline__ uint32_t smem_u32(const void* p) {
    uint32_t a;
    asm("{ .reg .u64 t; cvta.to.shared.u64 t, %1; cvt.u32.u64 %0, t; }" : "=r"(a) : "l"(p));
    return a;
}
__device__ __forceinline__ unsigned long long pk2(float x) {
    unsigned long long r;
    asm("mov.b64 %0, {%1, %1};" : "=l"(r) : "r"(__float_as_uint(x)));
    return r;
}
__device__ __forceinline__ unsigned long long pkpair(float a, float b) {
    unsigned long long r;
    asm("mov.b64 %0, {%1, %2};" : "=l"(r) : "r"(__float_as_uint(a)), "r"(__float_as_uint(b)));
    return r;
}
__device__ __forceinline__ void fma2(unsigned long long& d, unsigned long long a,
                                     unsigned long long b) {
    asm("fma.rn.f32x2 %0, %1, %2, %0;" : "+l"(d) : "l"(a), "l"(b));
}
__device__ __forceinline__ void unpk(unsigned long long v, float& lo, float& hi) {
    unsigned int l, h;
    asm("mov.b64 {%0, %1}, %2;" : "=r"(l), "=r"(h) : "l"(v));
    lo = __uint_as_float(l);
    hi = __uint_as_float(h);
}
__device__ __forceinline__ void mma16816(float* c, const uint32_t* a, const uint32_t* b) {
    asm volatile(
        "mma.sync.aligned.m16n8k16.row.col.f32.bf16.bf16.f32 "
        "{%0,%1,%2,%3}, {%4,%5,%6,%7}, {%8,%9}, {%0,%1,%2,%3};"
        : "+f"(c[0]), "+f"(c[1]), "+f"(c[2]), "+f"(c[3])
        : "r"(a[0]), "r"(a[1]), "r"(a[2]), "r"(a[3]), "r"(b[0]), "r"(b[1]));
}
#define CP_ASYNC16(dst, src) \
    asm volatile("cp.async.cg.shared.global [%0], [%1], 16;" :: "r"(dst), "l"(src))
#define CP_COMMIT() asm volatile("cp.async.commit_group;")
#define CP_WAIT0()  asm volatile("cp.async.wait_group 0;")

// ---- relative-position bias (transposed [h][m][n]) ---------------------------
__global__ void bias_kernel(const float* __restrict__ bt) {
    int idx = blockIdx.x * 256 + threadIdx.x;      // 0..32767
    if (idx >= 8 * 64 * 64) return;
    int h  = idx >> 12;
    int nm = idx & 4095;
    int m = nm >> 6, n = nm & 63;
    int dy = (n >> 3) - (m >> 3);
    int dx = (n & 7) - (m & 7);
    int r  = (dy + 7) * 15 + (dx + 7);
    g_bias[idx] = bt[r * 8 + h];
}

// ---- W transpose + bf16 hi/lo split: Wt[n][k] = W[k][n] ----------------------
__global__ void convw_kernel(const float* __restrict__ W, int Ncols) {
    int idx = blockIdx.x * 256 + threadIdx.x;
    if (idx >= Ncols * 256) return;
    int n = idx >> 8;
    int k = idx & 255;
    float v = W[k * Ncols + n];
    __nv_bfloat16 h = __float2bfloat16(v);
    g_Wthi[idx] = h;
    g_Wtlo[idx] = __float2bfloat16(v - __bfloat162float(h));
}

// ---- mma.sync GEMM:  C[M,N] = scale*(A[M,256] @ W + bias) --------------------
// 512 threads, block tile 128x128, warp tile 32x32 (4x4 warp grid), KC=32,
// ping-pong smem (A fp32->bf16 split in loader; B via cp.async of pre-split W).
// SMEM bytes: [0..512) bias, buffers at 1024 + b*40960:
//   Ah@0 Al@10240 Bh@20480 Bl@30720   (rows padded to 40 bf16 = 80B)
#define GSM_TOTAL (1024 + 2 * 40960)
#define AS 40

template <int N, int DSTSEL, int SRCSEL>
__global__ __launch_bounds__(512, 1)
void gemm_tc(const float* __restrict__ Ap, const float* __restrict__ bias,
             float* __restrict__ Cp, float scale) {
    extern __shared__ __align__(1024) char smem[];
    const uint32_t sb = smem_u32(smem);

    const float* A = (SRCSEL == 0) ? Ap : g_O;
    float* C = (DSTSEL == 0) ? g_Q : ((DSTSEL == 1) ? g_KV : Cp);

    const int tid  = threadIdx.x;
    const int wid  = tid >> 5, lane = tid & 31;
    const int g    = lane >> 2, tig = lane & 3;
    const int wm   = wid & 3, wn = wid >> 2;       // 4x4 warp grid
    const int n0   = blockIdx.x * 128;
    const long long m0 = (long long)blockIdx.y * 128;

    float* sBias = (float*)smem;
    if (tid < 128) sBias[tid] = bias[n0 + tid];

    float acc[2][4][4];
#pragma unroll
    for (int i = 0; i < 2; ++i)
#pragma unroll
        for (int j = 0; j < 4; ++j)
#pragma unroll
            for (int q = 0; q < 4; ++q) acc[i][j][q] = 0.f;

    // per-thread load coords
    const int arow = tid >> 2, aq = tid & 3;       // A: 128 rows x 4 f4 (x2 iters)
    const int brow = tid >> 2, bc = tid & 3;       // B: 128 rows x 4 lines of 16B

    // ---- loaders ----
    auto loadA_regs = [&](int kc, float4* r) {
#pragma unroll
        for (int i = 0; i < 2; ++i) {
            int row = arow + i * 128 * 0;          // arow in 0..127 already
            // 1024 float4 per chunk: idx = tid + i*512 -> row=idx>>3, q=idx&7
            int idx = tid + i * 512;
            row = idx >> 3;
            int q = idx & 7;
            r[i] = *reinterpret_cast<const float4*>(
                A + (m0 + row) * 256 + kc * 32 + q * 4);
        }
    };
    auto stsA = [&](int buf, const float4* r) {
        char* base = smem + 1024 + buf * 40960;
#pragma unroll
        for (int i = 0; i < 2; ++i) {
            int idx = tid + i * 512;
            int row = idx >> 3;
            int q = idx & 7;
            float4 v = r[i];
            __nv_bfloat16 h0 = __float2bfloat16(v.x), h1 = __float2bfloat16(v.y);
            __nv_bfloat16 h2 = __float2bfloat16(v.z), h3 = __float2bfloat16(v.w);
            __nv_bfloat162 hA(h0, h1), hB(h2, h3);
            __nv_bfloat162 lA(__float2bfloat16(v.x - __bfloat162float(h0)),
                              __float2bfloat16(v.y - __bfloat162float(h1)));
            __nv_bfloat162 lB(__float2bfloat16(v.z - __bfloat162float(h2)),
                              __float2bfloat16(v.w - __bfloat162float(h3)));
            int off = row * 80 + q * 8;
            *reinterpret_cast<uint2*>(base + off) =
                make_uint2(*reinterpret_cast<uint32_t*>(&hA),
                           *reinterpret_cast<uint32_t*>(&hB));
            *reinterpret_cast<uint2*>(base + 10240 + off) =
                make_uint2(*reinterpret_cast<uint32_t*>(&lA),
                           *reinterpret_cast<uint32_t*>(&lB));
        }
    };
    auto cpB = [&](int kc, int buf) {
        uint32_t base = sb + 1024 + buf * 40960;
        int off = brow * 80 + bc * 16;
        const __nv_bfloat16* sh = g_Wthi + (long long)(n0 + brow) * 256 + kc * 32 + bc * 8;
        const __nv_bfloat16* sl = g_Wtlo + (long long)(n0 + brow) * 256 + kc * 32 + bc * 8;
        CP_ASYNC16(base + 20480 + off, sh);
        CP_ASYNC16(base + 30720 + off, sl);
    };
    auto mma_buf = [&](int buf) {
        const __nv_bfloat16* Ahp = (const __nv_bfloat16*)(smem + 1024 + buf * 40960);
        const __nv_bfloat16* Alp = Ahp + 5120;
        const __nv_bfloat16* Bhp = Ahp + 10240;
        const __nv_bfloat16* Blp = Ahp + 15360;
#pragma unroll
        for (int ks = 0; ks < 2; ++ks) {
            const int k0 = ks * 16;
            uint32_t ah[2][4], al[2][4], bh[4][2], bl[4][2];
#pragma unroll
            for (int mf = 0; mf < 2; ++mf) {
                const __nv_bfloat16* p = Ahp + (wm * 32 + mf * 16 + g) * AS + k0 + tig * 2;
                const __nv_bfloat16* q = Alp + (wm * 32 + mf * 16 + g) * AS + k0 + tig * 2;
                ah[mf][0] = *(const uint32_t*)p;
                ah[mf][1] = *(const uint32_t*)(p + 8 * AS);
                ah[mf][2] = *(const uint32_t*)(p + 8);
                ah[mf][3] = *(const uint32_t*)(p + 8 * AS + 8);
                al[mf][0] = *(const uint32_t*)q;
                al[mf][1] = *(const uint32_t*)(q + 8 * AS);
                al[mf][2] = *(const uint32_t*)(q + 8);
                al[mf][3] = *(const uint32_t*)(q + 8 * AS + 8);
            }
#pragma unroll
            for (int nf = 0; nf < 4; ++nf) {
                const __nv_bfloat16* p = Bhp + (wn * 32 + nf * 8 + g) * AS + k0 + tig * 2;
                const __nv_bfloat16* q = Blp + (wn * 32 + nf * 8 + g) * AS + k0 + tig * 2;
                bh[nf][0] = *(const uint32_t*)p;
                bh[nf][1] = *(const uint32_t*)(p + 8);
                bl[nf][0] = *(const uint32_t*)q;
                bl[nf][1] = *(const uint32_t*)(q + 8);
            }
#pragma unroll
            for (int mf = 0; mf < 2; ++mf)
#pragma unroll
                for (int nf = 0; nf < 4; ++nf) {
                    mma16816(acc[mf][nf], ah[mf], bh[nf]);
                    mma16816(acc[mf][nf], ah[mf], bl[nf]);
                    mma16816(acc[mf][nf], al[mf], bh[nf]);
                }
        }
    };

    // ---- prologue: chunk 0 ----
    {
        float4 r[2];
        loadA_regs(0, r);
        cpB(0, 0);
        CP_COMMIT();
        stsA(0, r);
        CP_WAIT0();
        __syncthreads();
    }

    // ---- main loop over 8 k-chunks ----
#pragma unroll 1
    for (int kc = 0; kc < 8; ++kc) {
        const int buf = kc & 1;
        float4 r[2];
        if (kc < 7) {
            cpB(kc + 1, buf ^ 1);
            CP_COMMIT();
            loadA_regs(kc + 1, r);
        }
        mma_buf(buf);
        if (kc < 7) {
            stsA(buf ^ 1, r);
            CP_WAIT0();
            __syncthreads();
        }
    }

    // ---- epilogue ----
#pragma unroll
    for (int mf = 0; mf < 2; ++mf) {
#pragma unroll
        for (int nf = 0; nf < 4; ++nf) {
            const int cn = wn * 32 + nf * 8 + tig * 2;
            const float b0 = sBias[cn], b1 = sBias[cn + 1];
            const long long r0 = m0 + wm * 32 + mf * 16 + g;
            float* p0 = C + r0 * N + n0 + cn;
            float* p1 = C + (r0 + 8) * N + n0 + cn;
            *reinterpret_cast<float2*>(p0) =
                make_float2(scale * (acc[mf][nf][0] + b0), scale * (acc[mf][nf][1] + b1));
            *reinterpret_cast<float2*>(p1) =
                make_float2(scale * (acc[mf][nf][2] + b0), scale * (acc[mf][nf][3] + b1));
        }
    }
}

// ---- fused attention per (window, head) --------------------------------------
__global__ __launch_bounds__(64)
void attn_kernel() {
    __shared__ float sQ[64][33];
    __shared__ float sK[64][32];
    __shared__ float sV[64][32];

    const int w = blockIdx.x;
    const int h = blockIdx.y;
    const int tid = threadIdx.x;

    const float* qb = g_Q  + (long long)w * (64 * 256) + h * 32;
    const float* kb = g_KV + (long long)w * (64 * 512) + h * 32;
    const float* vb = kb + 256;

#pragma unroll
    for (int it = 0; it < 8; ++it) {
        int idx = tid + it * 64;
        int row = idx >> 3;
        int cq  = (idx & 7) << 2;
        float4 qv = *reinterpret_cast<const float4*>(qb + row * 256 + cq);
        sQ[row][cq + 0] = qv.x; sQ[row][cq + 1] = qv.y;
        sQ[row][cq + 2] = qv.z; sQ[row][cq + 3] = qv.w;
        *reinterpret_cast<float4*>(&sK[row][cq]) =
            *reinterpret_cast<const float4*>(kb + row * 512 + cq);
        *reinterpret_cast<float4*>(&sV[row][cq]) =
            *reinterpret_cast<const float4*>(vb + row * 512 + cq);
    }
    __syncthreads();

    const int n = tid;
    const float* bT = g_bias + h * 4096 + n;   // [h][m][n]: coalesced over n
    float s[64];
#pragma unroll
    for (int m = 0; m < 64; ++m) s[m] = bT[m * 64];

    unsigned long long qp[16];
#pragma unroll
    for (int j = 0; j < 16; ++j) qp[j] = pkpair(sQ[n][2 * j], sQ[n][2 * j + 1]);

#pragma unroll
    for (int m = 0; m < 64; ++m) {
        const unsigned long long* kr = reinterpret_cast<const unsigned long long*>(sK[m]);
        unsigned long long acc = 0ull;
#pragma unroll
        for (int j = 0; j < 16; ++j) fma2(acc, qp[j], kr[j]);
        float lo, hi;
        unpk(acc, lo, hi);
        s[m] += lo + hi;
    }

    float mx = s[0];
#pragma unroll
    for (int m = 1; m < 64; ++m) mx = fmaxf(mx, s[m]);
    float sum = 0.f;
#pragma unroll
    for (int m = 0; m < 64; ++m) {
        s[m] = __expf(s[m] - mx);
        sum += s[m];
    }
    const float inv = 1.f / sum;

    unsigned long long o2[16];
#pragma unroll
    for (int j = 0; j < 16; ++j) o2[j] = 0ull;
#pragma unroll
    for (int m = 0; m < 64; ++m) {
        const unsigned long long* vr = reinterpret_cast<const unsigned long long*>(sV[m]);
        unsigned long long p = pk2(s[m]);
#pragma unroll
        for (int j = 0; j < 16; ++j) fma2(o2[j], p, vr[j]);
    }

    float* ob = g_O + (long long)w * (64 * 256) + n * 256 + h * 32;
#pragma unroll
    for (int jq = 0; jq < 8; ++jq) {
        float a, b, c, d;
        unpk(o2[jq * 2 + 0], a, b);
        unpk(o2[jq * 2 + 1], c, d);
        *reinterpret_cast<float4*>(ob + jq * 4) =
            make_float4(a * inv, b * inv, c * inv, d * inv);
    }
}

// ---------------------------------------------------------------------------
extern "C" void kernel_launch(void* const* d_in, const int* in_sizes, int n_in,
                              void* d_out, int out_size) {
    const float* xq  = (const float*)d_in[0];
    const float* xs  = (const float*)d_in[1];
    const float* Wq  = (const float*)d_in[2];
    const float* bq  = (const float*)d_in[3];
    const float* Wkv = (const float*)d_in[4];
    const float* bkv = (const float*)d_in[5];
    const float* bt  = (const float*)d_in[6];
    const float* Wp  = (const float*)d_in[7];
    const float* bp  = (const float*)d_in[8];
    float* out = (float*)d_out;

    const int M = in_sizes[0] / 256;            // 262144
    const int B = M / 64;                       // 4096
    const float scale = 0.17677669529663687f;   // 32^-0.5

    cudaFuncSetAttribute(gemm_tc<256, 0, 0>,
                         cudaFuncAttributeMaxDynamicSharedMemorySize, GSM_TOTAL);
    cudaFuncSetAttribute(gemm_tc<512, 1, 0>,
                         cudaFuncAttributeMaxDynamicSharedMemorySize, GSM_TOTAL);
    cudaFuncSetAttribute(gemm_tc<256, 2, 1>,
                         cudaFuncAttributeMaxDynamicSharedMemorySize, GSM_TOTAL);

    bias_kernel<<<128, 256>>>(bt);

    convw_kernel<<<256, 256>>>(Wq, 256);
    gemm_tc<256, 0, 0><<<dim3(2, M / 128), 512, GSM_TOTAL>>>(xq, bq, nullptr, scale);

    convw_kernel<<<512, 256>>>(Wkv, 512);
    gemm_tc<512, 1, 0><<<dim3(4, M / 128), 512, GSM_TOTAL>>>(xs, bkv, nullptr, 1.f);

    attn_kernel<<<dim3(B, 8), 64>>>();

    convw_kernel<<<256, 256>>>(Wp, 256);
    gemm_tc<256, 2, 1><<<dim3(2, M / 128), 512, GSM_TOTAL>>>(nullptr, bp, out, 1.f);
}